// round 4
// baseline (speedup 1.0000x reference)
#include <cuda_runtime.h>
#include <cstdint>
#include <cstddef>

#define BB   2048
#define TT   128
#define FF   64
#define HH   256
#define G3   768
#define NJ   1024
#define OL   32
#define FCH  256
#define BM   16

// ---- device scratch ----
__device__ float g_hs[(size_t)TT * BB * HH];   // [t][b][j]
__device__ float g_Wt[320 * NJ];               // merged enc weights [k][j]
__device__ float g_Wd[HH * G3];                // dec_Whh^T [k][row]
__device__ float g_fc1t[HH * FCH];             // fc1_W^T [k][i]
__device__ float g_brz[512], g_bin[256], g_bhn[256];
__device__ float g_dbrz[512], g_dbin[256], g_dbhn[256];
__device__ float g_Abt[(size_t)BB * TT];
__device__ float g_Cbt[(size_t)BB * TT];
__device__ float g_prev[BB];

typedef unsigned long long u64;

__device__ __forceinline__ void fma2(u64 &d, u64 a, u64 b) {
    asm("fma.rn.f32x2 %0, %1, %2, %0;" : "+l"(d) : "l"(a), "l"(b));
}
__device__ __forceinline__ u64 pack2(float w) {
    u64 r; unsigned int u = __float_as_uint(w);
    asm("mov.b64 %0, {%1,%1};" : "=l"(r) : "r"(u));
    return r;
}
__device__ __forceinline__ float2 u2f(u64 v) {
    float2 r;
    asm("mov.b64 {%0, %1}, %2;" : "=f"(r.x), "=f"(r.y) : "l"(v));
    return r;
}
__device__ __forceinline__ float sigf(float x) { return 1.f / (1.f + __expf(-x)); }

// ---- prep: transposes + bias folding + prev0 ----
__global__ void prep_kernel(const float* __restrict__ x,
                            const float* __restrict__ eWih, const float* __restrict__ eWhh,
                            const float* __restrict__ ebih, const float* __restrict__ ebhh,
                            const float* __restrict__ dWhh,
                            const float* __restrict__ dbih, const float* __restrict__ dbhh,
                            const float* __restrict__ fc1W) {
    const int stride = gridDim.x * blockDim.x;
    const int id = blockIdx.x * blockDim.x + threadIdx.x;
    for (int i = id; i < 768 * 64; i += stride) {          // x-part: rz + i_n
        int j = i >> 6, k = i & 63;
        g_Wt[k * NJ + j] = eWih[j * 64 + k];
    }
    for (int i = id; i < 512 * 256; i += stride) {         // h-part rz
        int j = i >> 8, kh = i & 255;
        g_Wt[(64 + kh) * NJ + j] = eWhh[j * 256 + kh];
    }
    for (int i = id; i < 256 * 256; i += stride) {         // h-part h_n -> cols 768..1023
        int j = i >> 8, kh = i & 255;
        g_Wt[(64 + kh) * NJ + 768 + j] = eWhh[(512 + j) * 256 + kh];
    }
    for (int i = id; i < G3 * HH; i += stride) {
        int r = i >> 8, k = i & 255;
        g_Wd[k * G3 + r] = dWhh[i];
    }
    for (int i = id; i < FCH * HH; i += stride) {
        int r = i >> 8, k = i & 255;
        g_fc1t[k * FCH + r] = fc1W[i];
    }
    for (int i = id; i < 512; i += stride) {
        g_brz[i]  = ebih[i] + ebhh[i];
        g_dbrz[i] = dbih[i] + dbhh[i];
    }
    for (int i = id; i < 256; i += stride) {
        g_bin[i]  = ebih[512 + i];  g_bhn[i]  = ebhh[512 + i];
        g_dbin[i] = dbih[512 + i];  g_dbhn[i] = dbhh[512 + i];
    }
    for (int i = id; i < BB; i += stride)
        g_prev[i] = x[((size_t)i * TT + (TT - 1)) * FF];
}

// ---- encoder step: fused GEMM (f32x2 batch pairs) + GRU elementwise ----
#define ENC_SM (320 * 8 * 8 + BM * NJ * 4)   // 86016 bytes

__global__ void __launch_bounds__(256) enc_step_kernel(const float* __restrict__ x,
                                                       const float* __restrict__ h0,
                                                       int t) {
    extern __shared__ char smraw[];
    float2* As  = reinterpret_cast<float2*>(smraw);                     // [320][8] pairs
    float*  Asf = reinterpret_cast<float*>(smraw);
    float*  Gs  = reinterpret_cast<float*>(smraw + 320 * 8 * 8);        // [16][1024]
    const int tid = threadIdx.x;
    const int B0 = blockIdx.x * BM;
    const float* __restrict__ hprev = (t == 0) ? (h0 + (size_t)B0 * HH)
                                               : (g_hs + ((size_t)(t - 1) * BB + B0) * HH);
    for (int i = tid; i < BM * FF; i += 256) {
        int b = i >> 6, k = i & 63;
        Asf[(k * 8 + (b >> 1)) * 2 + (b & 1)] = x[((size_t)(B0 + b) * TT + t) * FF + k];
    }
    for (int i = tid; i < BM * HH; i += 256) {
        int b = i >> 8, k = i & 255;
        Asf[((64 + k) * 8 + (b >> 1)) * 2 + (b & 1)] = hprev[(size_t)b * HH + k];
    }
    __syncthreads();

    u64 aA0[8], aA1[8], aB[8], aC[8];
#pragma unroll
    for (int p = 0; p < 8; p++) { aA0[p] = 0; aA1[p] = 0; aB[p] = 0; aC[p] = 0; }

#pragma unroll 2
    for (int k = 0; k < 64; k++) {            // x-part: rz + i_n
        const float* w = g_Wt + (size_t)k * NJ;
        float2 wa = *reinterpret_cast<const float2*>(w + 2 * tid);
        u64 p0 = pack2(wa.x), p1 = pack2(wa.y), pb = pack2(w[512 + tid]);
#pragma unroll
        for (int p = 0; p < 8; p++) {
            u64 a2 = *reinterpret_cast<const u64*>(&As[k * 8 + p]);
            fma2(aA0[p], p0, a2); fma2(aA1[p], p1, a2); fma2(aB[p], pb, a2);
        }
    }
#pragma unroll 2
    for (int k = 64; k < 320; k++) {          // h-part: rz + h_n
        const float* w = g_Wt + (size_t)k * NJ;
        float2 wa = *reinterpret_cast<const float2*>(w + 2 * tid);
        u64 p0 = pack2(wa.x), p1 = pack2(wa.y), pc = pack2(w[768 + tid]);
#pragma unroll
        for (int p = 0; p < 8; p++) {
            u64 a2 = *reinterpret_cast<const u64*>(&As[k * 8 + p]);
            fma2(aA0[p], p0, a2); fma2(aA1[p], p1, a2); fma2(aC[p], pc, a2);
        }
    }
#pragma unroll
    for (int p = 0; p < 8; p++) {
        float2 f;
        f = u2f(aA0[p]); Gs[(2*p)*NJ + 2*tid]     = f.x; Gs[(2*p+1)*NJ + 2*tid]     = f.y;
        f = u2f(aA1[p]); Gs[(2*p)*NJ + 2*tid + 1] = f.x; Gs[(2*p+1)*NJ + 2*tid + 1] = f.y;
        f = u2f(aB[p]);  Gs[(2*p)*NJ + 512 + tid] = f.x; Gs[(2*p+1)*NJ + 512 + tid] = f.y;
        f = u2f(aC[p]);  Gs[(2*p)*NJ + 768 + tid] = f.x; Gs[(2*p+1)*NJ + 768 + tid] = f.y;
    }
    __syncthreads();

    const int j = tid;
    const float brz1 = g_brz[j], brz2 = g_brz[256 + j], bi = g_bin[j], bh = g_bhn[j];
    float* __restrict__ outp = g_hs + ((size_t)t * BB + B0) * HH;
#pragma unroll 4
    for (int b = 0; b < BM; b++) {
        float r  = sigf(Gs[b * NJ + j] + brz1);
        float z  = sigf(Gs[b * NJ + 256 + j] + brz2);
        float n  = tanhf(Gs[b * NJ + 512 + j] + bi + r * (Gs[b * NJ + 768 + j] + bh));
        float hp = Asf[((64 + j) * 8 + (b >> 1)) * 2 + (b & 1)];
        outp[(size_t)b * HH + j] = (1.f - z) * n + z * hp;
    }
}

// ---- attention precompute: A[b,t]=scale*Wq.hs, C[b,t]=scale*bq.hs ----
__global__ void __launch_bounds__(256) attn_pre_kernel(const float* __restrict__ wq,
                                                       const float* __restrict__ bq) {
    const int g = blockIdx.x * 8 + (threadIdx.x >> 5);
    const int lane = threadIdx.x & 31;
    const int b = g >> 7, t = g & 127;
    const float4* hv = reinterpret_cast<const float4*>(g_hs + ((size_t)t * BB + b) * HH);
    const float4* wv = reinterpret_cast<const float4*>(wq);
    const float4* bv = reinterpret_cast<const float4*>(bq);
    float a = 0.f, c = 0.f;
#pragma unroll
    for (int q = 0; q < 2; q++) {
        int idx = lane + q * 32;
        float4 h4 = hv[idx], w4 = wv[idx], b4 = bv[idx];
        a += h4.x*w4.x + h4.y*w4.y + h4.z*w4.z + h4.w*w4.w;
        c += h4.x*b4.x + h4.y*b4.y + h4.z*b4.z + h4.w*b4.w;
    }
#pragma unroll
    for (int o = 16; o > 0; o >>= 1) {
        a += __shfl_xor_sync(0xffffffffu, a, o);
        c += __shfl_xor_sync(0xffffffffu, c, o);
    }
    if (lane == 0) {
        g_Abt[(size_t)b * TT + t] = a * 0.0625f;
        g_Cbt[(size_t)b * TT + t] = c * 0.0625f;
    }
}

// ---- decoder step: scores->softmax->ctx->GRU->fc1->fc2 fused (static smem) ----
__global__ void __launch_bounds__(256) dec_step_kernel(const float* __restrict__ dWih,
                                                       const float* __restrict__ fc1b,
                                                       const float* __restrict__ fc2W,
                                                       const float* __restrict__ fc2b,
                                                       float* __restrict__ out, int step) {
    __shared__ char smraw[8192 + 16384 + 16384 + 64];
    float*  s    = reinterpret_cast<float*>(smraw);                     // [16][128]
    float2* ctxp = reinterpret_cast<float2*>(smraw + 8192);             // [256][8] pairs
    float*  f1s  = reinterpret_cast<float*>(smraw + 8192);              // overlays ctxp later
    float2* hdp  = reinterpret_cast<float2*>(smraw + 8192 + 16384);     // [256][8] pairs
    float*  prevs = reinterpret_cast<float*>(smraw + 8192 + 32768);     // [16]
    const int tid = threadIdx.x;
    const int B0 = blockIdx.x * BM;
    const int wid = tid >> 5, lane = tid & 31;
    if (tid < BM) prevs[tid] = g_prev[B0 + tid];
    __syncthreads();

    for (int i = tid; i < BM * TT; i += 256) {
        int b = i >> 7;
        s[i] = prevs[b] * g_Abt[(size_t)B0 * TT + i] + g_Cbt[(size_t)B0 * TT + i];
    }
    __syncthreads();

#pragma unroll
    for (int bb = 0; bb < 2; bb++) {          // softmax: warp handles 2 batches
        int b = wid * 2 + bb;
        float v0 = s[b*TT+lane], v1 = s[b*TT+lane+32], v2 = s[b*TT+lane+64], v3 = s[b*TT+lane+96];
        float m = fmaxf(fmaxf(v0, v1), fmaxf(v2, v3));
#pragma unroll
        for (int o = 16; o > 0; o >>= 1) m = fmaxf(m, __shfl_xor_sync(0xffffffffu, m, o));
        float e0 = __expf(v0-m), e1 = __expf(v1-m), e2 = __expf(v2-m), e3 = __expf(v3-m);
        float sum = e0 + e1 + e2 + e3;
#pragma unroll
        for (int o = 16; o > 0; o >>= 1) sum += __shfl_xor_sync(0xffffffffu, sum, o);
        float inv = 1.f / sum;
        s[b*TT+lane] = e0*inv; s[b*TT+lane+32] = e1*inv; s[b*TT+lane+64] = e2*inv; s[b*TT+lane+96] = e3*inv;
    }
    __syncthreads();

    {   // ctx[b][j] = sum_t w[b,t] * hs[t][b][j]
        const int jv = (tid & 63) * 4;
        const int bs = tid >> 6;
        float4 c0 = make_float4(0,0,0,0), c1 = c0, c2 = c0, c3 = c0;
        for (int t = 0; t < TT; t++) {
            const float* hb = g_hs + ((size_t)t * BB + B0) * HH + jv;
            float w0 = s[(bs+0)*TT+t], w1 = s[(bs+4)*TT+t], w2 = s[(bs+8)*TT+t], w3 = s[(bs+12)*TT+t];
            float4 h0 = *reinterpret_cast<const float4*>(hb + (size_t)(bs+0)*HH);
            float4 h1 = *reinterpret_cast<const float4*>(hb + (size_t)(bs+4)*HH);
            float4 h2 = *reinterpret_cast<const float4*>(hb + (size_t)(bs+8)*HH);
            float4 h3 = *reinterpret_cast<const float4*>(hb + (size_t)(bs+12)*HH);
            c0.x += w0*h0.x; c0.y += w0*h0.y; c0.z += w0*h0.z; c0.w += w0*h0.w;
            c1.x += w1*h1.x; c1.y += w1*h1.y; c1.z += w1*h1.z; c1.w += w1*h1.w;
            c2.x += w2*h2.x; c2.y += w2*h2.y; c2.z += w2*h2.z; c2.w += w2*h2.w;
            c3.x += w3*h3.x; c3.y += w3*h3.y; c3.z += w3*h3.z; c3.w += w3*h3.w;
        }
        float* cf = reinterpret_cast<float*>(ctxp);
        float4 cc[4] = {c0, c1, c2, c3};
#pragma unroll
        for (int q = 0; q < 4; q++) {
            int b = bs + 4 * q, p = b >> 1, par = b & 1;
            cf[((jv+0)*8+p)*2+par] = cc[q].x; cf[((jv+1)*8+p)*2+par] = cc[q].y;
            cf[((jv+2)*8+p)*2+par] = cc[q].z; cf[((jv+3)*8+p)*2+par] = cc[q].w;
        }
    }
    __syncthreads();

    const int j = tid;
    u64 ar[8], az[8], an[8];
#pragma unroll
    for (int p = 0; p < 8; p++) { ar[p] = 0; az[p] = 0; an[p] = 0; }
#pragma unroll 2
    for (int k = 0; k < HH; k++) {            // gh = ctx @ dec_Whh^T
        const float* w = g_Wd + (size_t)k * G3;
        u64 pr = pack2(w[j]), pz = pack2(w[256 + j]), pn = pack2(w[512 + j]);
#pragma unroll
        for (int p = 0; p < 8; p++) {
            u64 a2 = *reinterpret_cast<const u64*>(&ctxp[k * 8 + p]);
            fma2(ar[p], pr, a2); fma2(az[p], pz, a2); fma2(an[p], pn, a2);
        }
    }
    {   // decoder GRU elementwise (x = prev scalar, h = ctx)
        float dwr = dWih[j], dwz = dWih[256 + j], dwn = dWih[512 + j];
        float br = g_dbrz[j], bz = g_dbrz[256 + j], bi = g_dbin[j], bh = g_dbhn[j];
#pragma unroll
        for (int p = 0; p < 8; p++) {
            float2 fr = u2f(ar[p]), fz = u2f(az[p]), fn = u2f(an[p]);
            float2 cx = ctxp[j * 8 + p];
            float2 hd;
            float pv = prevs[2 * p];
            float r = sigf(pv * dwr + fr.x + br);
            float z = sigf(pv * dwz + fz.x + bz);
            float n = tanhf(pv * dwn + bi + r * (fn.x + bh));
            hd.x = (1.f - z) * n + z * cx.x;
            pv = prevs[2 * p + 1];
            r = sigf(pv * dwr + fr.y + br);
            z = sigf(pv * dwz + fz.y + bz);
            n = tanhf(pv * dwn + bi + r * (fn.y + bh));
            hd.y = (1.f - z) * n + z * cx.y;
            hdp[j * 8 + p] = hd;
        }
    }
    __syncthreads();   // hdp ready; ctxp region now reusable as f1s

    {   // fc1 + relu
        u64 f[8];
#pragma unroll
        for (int p = 0; p < 8; p++) f[p] = 0;
#pragma unroll 2
        for (int k = 0; k < HH; k++) {
            u64 wp = pack2(g_fc1t[(size_t)k * FCH + tid]);
#pragma unroll
            for (int p = 0; p < 8; p++)
                fma2(f[p], wp, *reinterpret_cast<const u64*>(&hdp[k * 8 + p]));
        }
        float b1 = fc1b[tid];
#pragma unroll
        for (int p = 0; p < 8; p++) {
            float2 v = u2f(f[p]);
            f1s[(2*p)*FCH + tid]   = fmaxf(v.x + b1, 0.f);
            f1s[(2*p+1)*FCH + tid] = fmaxf(v.y + b1, 0.f);
        }
    }
    __syncthreads();

    {   // fc2: warp reduces 2 batches
        float fb = fc2b[0];
#pragma unroll
        for (int bb = 0; bb < 2; bb++) {
            int b = wid * 2 + bb;
            float a = 0.f;
#pragma unroll
            for (int q = 0; q < 8; q++) {
                int i = lane + q * 32;
                a += f1s[b * FCH + i] * fc2W[i];
            }
#pragma unroll
            for (int o = 16; o > 0; o >>= 1) a += __shfl_xor_sync(0xffffffffu, a, o);
            if (lane == 0) {
                float v = a + fb;
                out[(size_t)(B0 + b) * OL + step] = v;
                g_prev[B0 + b] = v;
            }
        }
    }
}

extern "C" void kernel_launch(void* const* d_in, const int* in_sizes, int n_in,
                              void* d_out, int out_size) {
    const float* x      = (const float*)d_in[0];
    const float* h      = (const float*)d_in[1];
    const float* eWih   = (const float*)d_in[2];
    const float* eWhh   = (const float*)d_in[3];
    const float* ebih   = (const float*)d_in[4];
    const float* ebhh   = (const float*)d_in[5];
    const float* dWih   = (const float*)d_in[6];
    const float* dWhh   = (const float*)d_in[7];
    const float* dbih   = (const float*)d_in[8];
    const float* dbhh   = (const float*)d_in[9];
    const float* wq     = (const float*)d_in[10];
    const float* bq     = (const float*)d_in[11];
    const float* fc1W   = (const float*)d_in[12];
    const float* fc1b   = (const float*)d_in[13];
    const float* fc2W   = (const float*)d_in[14];
    const float* fc2b   = (const float*)d_in[15];
    float* out = (float*)d_out;

    cudaFuncSetAttribute(enc_step_kernel, cudaFuncAttributeMaxDynamicSharedMemorySize, ENC_SM);

    prep_kernel<<<256, 256>>>(x, eWih, eWhh, ebih, ebhh, dWhh, dbih, dbhh, fc1W);
    for (int t = 0; t < TT; t++)
        enc_step_kernel<<<BB / BM, 256, ENC_SM>>>(x, h, t);
    attn_pre_kernel<<<(BB * TT) / 8, 256>>>(wq, bq);
    for (int s = 0; s < OL; s++)
        dec_step_kernel<<<BB / BM, 256>>>(dWih, fc1b, fc2W, fc2b, out, s);
}

// round 5
// speedup vs baseline: 2.3687x; 2.3687x over previous
#include <cuda_runtime.h>
#include <cstdint>
#include <cstddef>

#define BB   2048
#define TT   128
#define FF   64
#define HH   256
#define G3   768
#define NJ   1024
#define OL   32
#define FCH  256
#define BM   16

// ---- device scratch ----
__device__ float  g_hs[(size_t)TT * BB * HH];      // [t][b][j]
__device__ float4 g_W6a[161 * 256];                // enc packed weights (2k per q)
__device__ float2 g_W6b[161 * 256];
__device__ float4 g_D6a[129 * 256];                // dec_Whh packed
__device__ float2 g_D6b[129 * 256];
__device__ float2 g_F2 [129 * 256];                // fc1 packed
__device__ float  g_brz[512], g_bin[256], g_bhn[256];
__device__ float  g_dbrz[512], g_dbin[256], g_dbhn[256];
__device__ float  g_Abt[(size_t)BB * TT];
__device__ float  g_Cbt[(size_t)BB * TT];
__device__ float  g_prev[BB];

typedef unsigned long long u64;

__device__ __forceinline__ void fma2(u64 &d, u64 a, u64 b) {
    asm("fma.rn.f32x2 %0, %1, %2, %0;" : "+l"(d) : "l"(a), "l"(b));
}
__device__ __forceinline__ u64 pack2(float w) {
    u64 r; unsigned int u = __float_as_uint(w);
    asm("mov.b64 %0, {%1,%1};" : "=l"(r) : "r"(u));
    return r;
}
__device__ __forceinline__ float2 u2f(u64 v) {
    float2 r;
    asm("mov.b64 {%0, %1}, %2;" : "=f"(r.x), "=f"(r.y) : "l"(v));
    return r;
}
__device__ __forceinline__ float sigf(float x) { return 1.f / (1.f + __expf(-x)); }

// ---- prep: packed weight streams + bias folding + prev0 ----
__global__ void prep_kernel(const float* __restrict__ x,
                            const float* __restrict__ eWih, const float* __restrict__ eWhh,
                            const float* __restrict__ ebih, const float* __restrict__ ebhh,
                            const float* __restrict__ dWhh,
                            const float* __restrict__ dbih, const float* __restrict__ dbhh,
                            const float* __restrict__ fc1W) {
    const int stride = gridDim.x * blockDim.x;
    const int id = blockIdx.x * blockDim.x + threadIdx.x;
    // encoder 6-pack: per q (covers k0=2q, k1=2q+1), per thread tid:
    // slots: rz_even(k0), rz_odd(k0), s2(k0), rz_even(k1) | rz_odd(k1), s2(k1)
    for (int i = id; i < 160 * 256; i += stride) {
        int q = i >> 8, tid = i & 255;
        int k0 = 2 * q, k1 = k0 + 1;
        auto WRZ = [&](int j, int k) {
            return k < 64 ? eWih[j * 64 + k] : eWhh[j * 256 + (k - 64)];
        };
        auto S2 = [&](int k) {
            return k < 64 ? eWih[(512 + tid) * 64 + k] : eWhh[(512 + tid) * 256 + (k - 64)];
        };
        g_W6a[i] = make_float4(WRZ(2 * tid, k0), WRZ(2 * tid + 1, k0), S2(k0), WRZ(2 * tid, k1));
        g_W6b[i] = make_float2(WRZ(2 * tid + 1, k1), S2(k1));
    }
    // decoder packs
    for (int i = id; i < 128 * 256; i += stride) {
        int q = i >> 8, j = i & 255;
        int k0 = 2 * q, k1 = k0 + 1;
        g_D6a[i] = make_float4(dWhh[j * 256 + k0], dWhh[(256 + j) * 256 + k0],
                               dWhh[(512 + j) * 256 + k0], dWhh[j * 256 + k1]);
        g_D6b[i] = make_float2(dWhh[(256 + j) * 256 + k1], dWhh[(512 + j) * 256 + k1]);
        g_F2[i]  = make_float2(fc1W[j * 256 + k0], fc1W[j * 256 + k1]);
    }
    for (int i = id; i < 512; i += stride) {
        g_brz[i]  = ebih[i] + ebhh[i];
        g_dbrz[i] = dbih[i] + dbhh[i];
    }
    for (int i = id; i < 256; i += stride) {
        g_bin[i]  = ebih[512 + i];  g_bhn[i]  = ebhh[512 + i];
        g_dbin[i] = dbih[512 + i];  g_dbhn[i] = dbhh[512 + i];
    }
    for (int i = id; i < BB; i += stride)
        g_prev[i] = x[((size_t)i * TT + (TT - 1)) * FF];
}

// 2-k FMA body: wa/wb hold the 6 weights, AS is the third accumulator set
#define ENC_STEP6(K0, AS) do {                                                             \
    const double2* _av0 = reinterpret_cast<const double2*>(As + (K0) * 8);                 \
    const double2* _av1 = reinterpret_cast<const double2*>(As + ((K0) + 1) * 8);           \
    u64 _p00 = pack2(wa.x), _p01 = pack2(wa.y), _p02 = pack2(wa.z);                        \
    u64 _p10 = pack2(wa.w), _p11 = pack2(wb.x), _p12 = pack2(wb.y);                        \
    _Pragma("unroll")                                                                      \
    for (int _h = 0; _h < 4; _h++) {                                                       \
        double2 _d0 = _av0[_h], _d1 = _av1[_h];                                            \
        u64 _a00 = __double_as_longlong(_d0.x), _a01 = __double_as_longlong(_d0.y);        \
        u64 _a10 = __double_as_longlong(_d1.x), _a11 = __double_as_longlong(_d1.y);        \
        fma2(aA0[2*_h],   _p00, _a00); fma2(aA1[2*_h],   _p01, _a00); fma2(AS[2*_h],   _p02, _a00); \
        fma2(aA0[2*_h+1], _p00, _a01); fma2(aA1[2*_h+1], _p01, _a01); fma2(AS[2*_h+1], _p02, _a01); \
        fma2(aA0[2*_h],   _p10, _a10); fma2(aA1[2*_h],   _p11, _a10); fma2(AS[2*_h],   _p12, _a10); \
        fma2(aA0[2*_h+1], _p10, _a11); fma2(aA1[2*_h+1], _p11, _a11); fma2(AS[2*_h+1], _p12, _a11); \
    }                                                                                      \
} while (0)

// ---- persistent encoder: all 128 timesteps, h lives in shared memory ----
#define ENC_SM (320 * 8 * 8 + BM * NJ * 4)   // 86016 bytes

__global__ void __launch_bounds__(256) enc_all_kernel(const float* __restrict__ x,
                                                      const float* __restrict__ h0) {
    extern __shared__ char smraw[];
    float2* As  = reinterpret_cast<float2*>(smraw);               // [320][8] batch pairs
    float*  Asf = reinterpret_cast<float*>(smraw);
    float*  Gs  = reinterpret_cast<float*>(smraw + 320 * 8 * 8);  // [16][1024]
    const int tid = threadIdx.x;
    const int B0 = blockIdx.x * BM;

    // init h into As h-part
    for (int i = tid; i < BM * HH; i += 256) {
        int b = i >> 8, k = i & 255;
        Asf[((64 + k) * 8 + (b >> 1)) * 2 + (b & 1)] = h0[(size_t)(B0 + b) * HH + k];
    }
    const float brz1 = g_brz[tid], brz2 = g_brz[256 + tid];
    const float bi = g_bin[tid], bh = g_bhn[tid];

    for (int t = 0; t < TT; t++) {
        // load x_t
        for (int i = tid; i < BM * FF; i += 256) {
            int b = i >> 6, k = i & 63;
            Asf[(k * 8 + (b >> 1)) * 2 + (b & 1)] = x[((size_t)(B0 + b) * TT + t) * FF + k];
        }
        __syncthreads();

        u64 aA0[8], aA1[8], aB[8], aC[8];
#pragma unroll
        for (int p = 0; p < 8; p++) { aA0[p] = 0; aA1[p] = 0; aB[p] = 0; aC[p] = 0; }

        float4 wa = g_W6a[tid];
        float2 wb = g_W6b[tid];
        for (int q = 0; q < 32; q++) {             // x-part: rz + i_n
            float4 wan = g_W6a[(q + 1) * 256 + tid];
            float2 wbn = g_W6b[(q + 1) * 256 + tid];
            ENC_STEP6(2 * q, aB);
            wa = wan; wb = wbn;
        }
        for (int q = 32; q < 160; q++) {           // h-part: rz + h_n
            float4 wan = g_W6a[(q + 1) * 256 + tid];
            float2 wbn = g_W6b[(q + 1) * 256 + tid];
            ENC_STEP6(2 * q, aC);
            wa = wan; wb = wbn;
        }
#pragma unroll
        for (int p = 0; p < 8; p++) {
            float2 f;
            f = u2f(aA0[p]); Gs[(2*p)*NJ + 2*tid]     = f.x; Gs[(2*p+1)*NJ + 2*tid]     = f.y;
            f = u2f(aA1[p]); Gs[(2*p)*NJ + 2*tid + 1] = f.x; Gs[(2*p+1)*NJ + 2*tid + 1] = f.y;
            f = u2f(aB[p]);  Gs[(2*p)*NJ + 512 + tid] = f.x; Gs[(2*p+1)*NJ + 512 + tid] = f.y;
            f = u2f(aC[p]);  Gs[(2*p)*NJ + 768 + tid] = f.x; Gs[(2*p+1)*NJ + 768 + tid] = f.y;
        }
        __syncthreads();

        // GRU elementwise: thread = hidden index j; update h in-place in smem
        const int j = tid;
        float* __restrict__ outp = g_hs + ((size_t)t * BB + B0) * HH;
#pragma unroll 4
        for (int b = 0; b < BM; b++) {
            float r  = sigf(Gs[b * NJ + j] + brz1);
            float z  = sigf(Gs[b * NJ + 256 + j] + brz2);
            float n  = tanhf(Gs[b * NJ + 512 + j] + bi + r * (Gs[b * NJ + 768 + j] + bh));
            int idx = ((64 + j) * 8 + (b >> 1)) * 2 + (b & 1);
            float hp = Asf[idx];
            float hn = (1.f - z) * n + z * hp;
            Asf[idx] = hn;
            outp[(size_t)b * HH + j] = hn;
        }
        // loop-top __syncthreads() covers h-writes -> next GEMM reads
    }
}

// ---- attention precompute: A[b,t]=scale*Wq.hs, C[b,t]=scale*bq.hs ----
__global__ void __launch_bounds__(256) attn_pre_kernel(const float* __restrict__ wq,
                                                       const float* __restrict__ bq) {
    const int g = blockIdx.x * 8 + (threadIdx.x >> 5);
    const int lane = threadIdx.x & 31;
    const int b = g >> 7, t = g & 127;
    const float4* hv = reinterpret_cast<const float4*>(g_hs + ((size_t)t * BB + b) * HH);
    const float4* wv = reinterpret_cast<const float4*>(wq);
    const float4* bv = reinterpret_cast<const float4*>(bq);
    float a = 0.f, c = 0.f;
#pragma unroll
    for (int q = 0; q < 2; q++) {
        int idx = lane + q * 32;
        float4 h4 = hv[idx], w4 = wv[idx], b4 = bv[idx];
        a += h4.x*w4.x + h4.y*w4.y + h4.z*w4.z + h4.w*w4.w;
        c += h4.x*b4.x + h4.y*b4.y + h4.z*b4.z + h4.w*b4.w;
    }
#pragma unroll
    for (int o = 16; o > 0; o >>= 1) {
        a += __shfl_xor_sync(0xffffffffu, a, o);
        c += __shfl_xor_sync(0xffffffffu, c, o);
    }
    if (lane == 0) {
        g_Abt[(size_t)b * TT + t] = a * 0.0625f;
        g_Cbt[(size_t)b * TT + t] = c * 0.0625f;
    }
}

#define DEC_STEP6(K0) do {                                                                 \
    const double2* _av0 = reinterpret_cast<const double2*>(ctxp + (K0) * 8);               \
    const double2* _av1 = reinterpret_cast<const double2*>(ctxp + ((K0) + 1) * 8);         \
    u64 _p00 = pack2(wa.x), _p01 = pack2(wa.y), _p02 = pack2(wa.z);                        \
    u64 _p10 = pack2(wa.w), _p11 = pack2(wb.x), _p12 = pack2(wb.y);                        \
    _Pragma("unroll")                                                                      \
    for (int _h = 0; _h < 4; _h++) {                                                       \
        double2 _d0 = _av0[_h], _d1 = _av1[_h];                                            \
        u64 _a00 = __double_as_longlong(_d0.x), _a01 = __double_as_longlong(_d0.y);        \
        u64 _a10 = __double_as_longlong(_d1.x), _a11 = __double_as_longlong(_d1.y);        \
        fma2(ar[2*_h],   _p00, _a00); fma2(az[2*_h],   _p01, _a00); fma2(an[2*_h],   _p02, _a00); \
        fma2(ar[2*_h+1], _p00, _a01); fma2(az[2*_h+1], _p01, _a01); fma2(an[2*_h+1], _p02, _a01); \
        fma2(ar[2*_h],   _p10, _a10); fma2(az[2*_h],   _p11, _a10); fma2(an[2*_h],   _p12, _a10); \
        fma2(ar[2*_h+1], _p10, _a11); fma2(az[2*_h+1], _p11, _a11); fma2(an[2*_h+1], _p12, _a11); \
    }                                                                                      \
} while (0)

// ---- persistent decoder: all 32 steps fused ----
__global__ void __launch_bounds__(256) dec_all_kernel(const float* __restrict__ dWih,
                                                      const float* __restrict__ fc1b,
                                                      const float* __restrict__ fc2W,
                                                      const float* __restrict__ fc2b,
                                                      float* __restrict__ out) {
    __shared__ char smraw[8192 + 16384 + 16384 + 64];
    float*  s     = reinterpret_cast<float*>(smraw);                 // [16][128]
    float2* ctxp  = reinterpret_cast<float2*>(smraw + 8192);         // [256][8] pairs
    float*  f1s   = reinterpret_cast<float*>(smraw + 8192);          // overlays ctxp
    float2* hdp   = reinterpret_cast<float2*>(smraw + 8192 + 16384); // [256][8] pairs
    float*  prevs = reinterpret_cast<float*>(smraw + 8192 + 32768);  // [16]
    const int tid = threadIdx.x;
    const int B0 = blockIdx.x * BM;
    const int wid = tid >> 5, lane = tid & 31;
    const int j = tid;

    if (tid < BM) prevs[tid] = g_prev[B0 + tid];
    const float dwr = dWih[j], dwz = dWih[256 + j], dwn = dWih[512 + j];
    const float br = g_dbrz[j], bz = g_dbrz[256 + j], bi = g_dbin[j], bh = g_dbhn[j];
    const float b1 = fc1b[tid], fb = fc2b[0];
    float w2r[8];
#pragma unroll
    for (int q = 0; q < 8; q++) w2r[q] = fc2W[lane + 32 * q];
    __syncthreads();

    for (int step = 0; step < OL; step++) {
        // scores = prev*A + C
        for (int i = tid; i < BM * TT; i += 256) {
            int b = i >> 7;
            s[i] = prevs[b] * g_Abt[(size_t)B0 * TT + i] + g_Cbt[(size_t)B0 * TT + i];
        }
        __syncthreads();

#pragma unroll
        for (int bb = 0; bb < 2; bb++) {          // softmax: warp handles 2 batches
            int b = wid * 2 + bb;
            float v0 = s[b*TT+lane], v1 = s[b*TT+lane+32], v2 = s[b*TT+lane+64], v3 = s[b*TT+lane+96];
            float m = fmaxf(fmaxf(v0, v1), fmaxf(v2, v3));
#pragma unroll
            for (int o = 16; o > 0; o >>= 1) m = fmaxf(m, __shfl_xor_sync(0xffffffffu, m, o));
            float e0 = __expf(v0-m), e1 = __expf(v1-m), e2 = __expf(v2-m), e3 = __expf(v3-m);
            float sum = e0 + e1 + e2 + e3;
#pragma unroll
            for (int o = 16; o > 0; o >>= 1) sum += __shfl_xor_sync(0xffffffffu, sum, o);
            float inv = 1.f / sum;
            s[b*TT+lane] = e0*inv; s[b*TT+lane+32] = e1*inv; s[b*TT+lane+64] = e2*inv; s[b*TT+lane+96] = e3*inv;
        }
        __syncthreads();

        {   // ctx[b][j] = sum_t w[b,t] * hs[t][b][j]  (DRAM pass)
            const int jv = (tid & 63) * 4;
            const int bs = tid >> 6;
            float4 c0 = make_float4(0,0,0,0), c1 = c0, c2 = c0, c3 = c0;
            for (int t = 0; t < TT; t++) {
                const float* hb = g_hs + ((size_t)t * BB + B0) * HH + jv;
                float w0 = s[(bs+0)*TT+t], w1 = s[(bs+4)*TT+t], w2 = s[(bs+8)*TT+t], w3 = s[(bs+12)*TT+t];
                float4 h0 = *reinterpret_cast<const float4*>(hb + (size_t)(bs+0)*HH);
                float4 h1 = *reinterpret_cast<const float4*>(hb + (size_t)(bs+4)*HH);
                float4 h2 = *reinterpret_cast<const float4*>(hb + (size_t)(bs+8)*HH);
                float4 h3 = *reinterpret_cast<const float4*>(hb + (size_t)(bs+12)*HH);
                c0.x += w0*h0.x; c0.y += w0*h0.y; c0.z += w0*h0.z; c0.w += w0*h0.w;
                c1.x += w1*h1.x; c1.y += w1*h1.y; c1.z += w1*h1.z; c1.w += w1*h1.w;
                c2.x += w2*h2.x; c2.y += w2*h2.y; c2.z += w2*h2.z; c2.w += w2*h2.w;
                c3.x += w3*h3.x; c3.y += w3*h3.y; c3.z += w3*h3.z; c3.w += w3*h3.w;
            }
            float* cf = reinterpret_cast<float*>(ctxp);
            float4 cc[4] = {c0, c1, c2, c3};
#pragma unroll
            for (int q = 0; q < 4; q++) {
                int b = bs + 4 * q, p = b >> 1, par = b & 1;
                cf[((jv+0)*8+p)*2+par] = cc[q].x; cf[((jv+1)*8+p)*2+par] = cc[q].y;
                cf[((jv+2)*8+p)*2+par] = cc[q].z; cf[((jv+3)*8+p)*2+par] = cc[q].w;
            }
        }
        __syncthreads();

        u64 ar[8], az[8], an[8];
#pragma unroll
        for (int p = 0; p < 8; p++) { ar[p] = 0; az[p] = 0; an[p] = 0; }
        {   // gh = ctx @ dec_Whh^T with prefetched packed weights
            float4 wa = g_D6a[tid];
            float2 wb = g_D6b[tid];
            for (int q = 0; q < 128; q++) {
                float4 wan = g_D6a[(q + 1) * 256 + tid];
                float2 wbn = g_D6b[(q + 1) * 256 + tid];
                DEC_STEP6(2 * q);
                wa = wan; wb = wbn;
            }
        }
        {   // decoder GRU elementwise (x = prev scalar, h = ctx)
#pragma unroll
            for (int p = 0; p < 8; p++) {
                float2 fr = u2f(ar[p]), fz = u2f(az[p]), fn = u2f(an[p]);
                float2 cx = ctxp[j * 8 + p];
                float2 hd;
                float pv = prevs[2 * p];
                float r = sigf(pv * dwr + fr.x + br);
                float z = sigf(pv * dwz + fz.x + bz);
                float n = tanhf(pv * dwn + bi + r * (fn.x + bh));
                hd.x = (1.f - z) * n + z * cx.x;
                pv = prevs[2 * p + 1];
                r = sigf(pv * dwr + fr.y + br);
                z = sigf(pv * dwz + fz.y + bz);
                n = tanhf(pv * dwn + bi + r * (fn.y + bh));
                hd.y = (1.f - z) * n + z * cx.y;
                hdp[j * 8 + p] = hd;
            }
        }
        __syncthreads();   // hdp ready; ctxp region now reusable as f1s

        {   // fc1 + relu
            u64 f[8];
#pragma unroll
            for (int p = 0; p < 8; p++) f[p] = 0;
            float2 wf = g_F2[tid];
            for (int q = 0; q < 128; q++) {
                float2 wfn = g_F2[(q + 1) * 256 + tid];
                const double2* hv0 = reinterpret_cast<const double2*>(hdp + (2 * q) * 8);
                const double2* hv1 = reinterpret_cast<const double2*>(hdp + (2 * q + 1) * 8);
                u64 w0 = pack2(wf.x), w1 = pack2(wf.y);
#pragma unroll
                for (int h = 0; h < 4; h++) {
                    double2 d0 = hv0[h], d1 = hv1[h];
                    fma2(f[2*h],   w0, __double_as_longlong(d0.x));
                    fma2(f[2*h+1], w0, __double_as_longlong(d0.y));
                    fma2(f[2*h],   w1, __double_as_longlong(d1.x));
                    fma2(f[2*h+1], w1, __double_as_longlong(d1.y));
                }
                wf = wfn;
            }
#pragma unroll
            for (int p = 0; p < 8; p++) {
                float2 v = u2f(f[p]);
                f1s[(2*p)*FCH + tid]   = fmaxf(v.x + b1, 0.f);
                f1s[(2*p+1)*FCH + tid] = fmaxf(v.y + b1, 0.f);
            }
        }
        __syncthreads();

        {   // fc2: warp reduces 2 batches; carry prev in smem
#pragma unroll
            for (int bb = 0; bb < 2; bb++) {
                int b = wid * 2 + bb;
                float a = 0.f;
#pragma unroll
                for (int q = 0; q < 8; q++)
                    a += f1s[b * FCH + lane + 32 * q] * w2r[q];
#pragma unroll
                for (int o = 16; o > 0; o >>= 1) a += __shfl_xor_sync(0xffffffffu, a, o);
                if (lane == 0) {
                    float v = a + fb;
                    out[(size_t)(B0 + b) * OL + step] = v;
                    prevs[b] = v;
                }
            }
        }
        __syncthreads();   // prevs ready for next step; f1s free for next ctx
    }
}

extern "C" void kernel_launch(void* const* d_in, const int* in_sizes, int n_in,
                              void* d_out, int out_size) {
    const float* x      = (const float*)d_in[0];
    const float* h      = (const float*)d_in[1];
    const float* eWih   = (const float*)d_in[2];
    const float* eWhh   = (const float*)d_in[3];
    const float* ebih   = (const float*)d_in[4];
    const float* ebhh   = (const float*)d_in[5];
    const float* dWih   = (const float*)d_in[6];
    const float* dWhh   = (const float*)d_in[7];
    const float* dbih   = (const float*)d_in[8];
    const float* dbhh   = (const float*)d_in[9];
    const float* wq     = (const float*)d_in[10];
    const float* bq     = (const float*)d_in[11];
    const float* fc1W   = (const float*)d_in[12];
    const float* fc1b   = (const float*)d_in[13];
    const float* fc2W   = (const float*)d_in[14];
    const float* fc2b   = (const float*)d_in[15];
    float* out = (float*)d_out;

    cudaFuncSetAttribute(enc_all_kernel, cudaFuncAttributeMaxDynamicSharedMemorySize, ENC_SM);

    prep_kernel<<<256, 256>>>(x, eWih, eWhh, ebih, ebhh, dWhh, dbih, dbhh, fc1W);
    enc_all_kernel<<<BB / BM, 256, ENC_SM>>>(x, h);
    attn_pre_kernel<<<(BB * TT) / 8, 256>>>(wq, bq);
    dec_all_kernel<<<BB / BM, 256>>>(dWih, fc1b, fc2W, fc2b, out);
}

// round 7
// speedup vs baseline: 2.8595x; 1.2072x over previous
#include <cuda_runtime.h>
#include <cuda_fp16.h>
#include <cstdint>
#include <cstddef>

#define BB   2048
#define TT   128
#define FF   64
#define HH   256
#define G3   768
#define OL   32
#define FCH  256
#define BM   16
#define ASP  10          // float2 pairs per As row (8 used + 2 pad -> 80B rows, 16B aligned)

// ---- device scratch ----
__device__ __half g_hsh[(size_t)TT * BB * HH];          // [t][b][j] fp16 (ctx source)
__device__ float4 g_W6a[160 * 256];                     // enc packed weights (2k per q)
__device__ float2 g_W6b[160 * 256];
__device__ float4 g_D6a[128 * 256];                     // dec_Whh packed
__device__ float2 g_D6b[128 * 256];
__device__ float2 g_F2 [128 * 256];                     // fc1 packed
__device__ float  g_brz[512], g_bin[256], g_bhn[256];
__device__ float  g_dbrz[512], g_dbin[256], g_dbhn[256];
__device__ float  g_Abt[(size_t)BB * TT];
__device__ float  g_Cbt[(size_t)BB * TT];
__device__ float  g_prev[BB];

typedef unsigned long long u64;

__device__ __forceinline__ void fma2(u64 &d, u64 a, u64 b) {
    asm("fma.rn.f32x2 %0, %1, %2, %0;" : "+l"(d) : "l"(a), "l"(b));
}
__device__ __forceinline__ u64 pack2(float w) {
    u64 r; unsigned int u = __float_as_uint(w);
    asm("mov.b64 %0, {%1,%1};" : "=l"(r) : "r"(u));
    return r;
}
__device__ __forceinline__ float2 u2f(u64 v) {
    float2 r;
    asm("mov.b64 {%0, %1}, %2;" : "=f"(r.x), "=f"(r.y) : "l"(v));
    return r;
}
// two fp16 (packed in u32) -> packed f32x2 (exact widening)
__device__ __forceinline__ u64 hfp(unsigned v) {
    __half2 h2 = *reinterpret_cast<__half2*>(&v);
    float2 f = __half22float2(h2);
    u64 r;
    asm("mov.b64 %0, {%1,%2};" : "=l"(r) : "f"(f.x), "f"(f.y));
    return r;
}
__device__ __forceinline__ float sigf(float x) { return 1.f / (1.f + __expf(-x)); }

// ---- prep: packed weight streams + bias folding + prev0 ----
__global__ void prep_kernel(const float* __restrict__ x,
                            const float* __restrict__ eWih, const float* __restrict__ eWhh,
                            const float* __restrict__ ebih, const float* __restrict__ ebhh,
                            const float* __restrict__ dWhh,
                            const float* __restrict__ dbih, const float* __restrict__ dbhh,
                            const float* __restrict__ fc1W) {
    const int stride = gridDim.x * blockDim.x;
    const int id = blockIdx.x * blockDim.x + threadIdx.x;
    // encoder pack: thread j owns gate rows j (r), 256+j (z), 512+j (i_n / h_n)
    for (int i = id; i < 160 * 256; i += stride) {
        int q = i >> 8, j = i & 255;
        float wr0, wz0, w30, wr1, wz1, w31;
        if (q < 32) {
            int k0 = 2 * q, k1 = k0 + 1;
            wr0 = eWih[j * 64 + k0];         wr1 = eWih[j * 64 + k1];
            wz0 = eWih[(256 + j) * 64 + k0]; wz1 = eWih[(256 + j) * 64 + k1];
            w30 = eWih[(512 + j) * 64 + k0]; w31 = eWih[(512 + j) * 64 + k1];
        } else {
            int k0 = 2 * q - 64, k1 = k0 + 1;
            wr0 = eWhh[j * 256 + k0];         wr1 = eWhh[j * 256 + k1];
            wz0 = eWhh[(256 + j) * 256 + k0]; wz1 = eWhh[(256 + j) * 256 + k1];
            w30 = eWhh[(512 + j) * 256 + k0]; w31 = eWhh[(512 + j) * 256 + k1];
        }
        g_W6a[i] = make_float4(wr0, wz0, w30, wr1);
        g_W6b[i] = make_float2(wz1, w31);
    }
    for (int i = id; i < 128 * 256; i += stride) {
        int q = i >> 8, j = i & 255;
        int k0 = 2 * q, k1 = k0 + 1;
        g_D6a[i] = make_float4(dWhh[j * 256 + k0], dWhh[(256 + j) * 256 + k0],
                               dWhh[(512 + j) * 256 + k0], dWhh[j * 256 + k1]);
        g_D6b[i] = make_float2(dWhh[(256 + j) * 256 + k1], dWhh[(512 + j) * 256 + k1]);
        g_F2[i]  = make_float2(fc1W[j * 256 + k0], fc1W[j * 256 + k1]);
    }
    for (int i = id; i < 512; i += stride) {
        g_brz[i]  = ebih[i] + ebhh[i];
        g_dbrz[i] = dbih[i] + dbhh[i];
    }
    for (int i = id; i < 256; i += stride) {
        g_bin[i]  = ebih[512 + i];  g_bhn[i]  = ebhh[512 + i];
        g_dbin[i] = dbih[512 + i];  g_dbhn[i] = dbhh[512 + i];
    }
    for (int i = id; i < BB; i += stride)
        g_prev[i] = x[((size_t)i * TT + (TT - 1)) * FF];
}

// 2-k FMA body: As row = 2q (x rows 0..63, h rows 64..319)
#define ENC_STEP6(K0, AS) do {                                                             \
    const double2* _av0 = reinterpret_cast<const double2*>(As + (K0) * ASP);               \
    const double2* _av1 = reinterpret_cast<const double2*>(As + ((K0) + 1) * ASP);         \
    u64 _p00 = pack2(wa.x), _p01 = pack2(wa.y), _p02 = pack2(wa.z);                        \
    u64 _p10 = pack2(wa.w), _p11 = pack2(wb.x), _p12 = pack2(wb.y);                        \
    _Pragma("unroll")                                                                      \
    for (int _h = 0; _h < 4; _h++) {                                                       \
        double2 _d0 = _av0[_h], _d1 = _av1[_h];                                            \
        u64 _a00 = __double_as_longlong(_d0.x), _a01 = __double_as_longlong(_d0.y);        \
        u64 _a10 = __double_as_longlong(_d1.x), _a11 = __double_as_longlong(_d1.y);        \
        fma2(aR[2*_h],   _p00, _a00); fma2(aZ[2*_h],   _p01, _a00); fma2(AS[2*_h],   _p02, _a00); \
        fma2(aR[2*_h+1], _p00, _a01); fma2(aZ[2*_h+1], _p01, _a01); fma2(AS[2*_h+1], _p02, _a01); \
        fma2(aR[2*_h],   _p10, _a10); fma2(aZ[2*_h],   _p11, _a10); fma2(AS[2*_h],   _p12, _a10); \
        fma2(aR[2*_h+1], _p10, _a11); fma2(aZ[2*_h+1], _p11, _a11); fma2(AS[2*_h+1], _p12, _a11); \
    }                                                                                      \
} while (0)

// ---- persistent encoder: all 128 steps, h in smem, gates in registers,
//      exact attention A/C computed in-kernel ----
__global__ void __launch_bounds__(256) enc_all_kernel(const float* __restrict__ x,
                                                      const float* __restrict__ h0,
                                                      const float* __restrict__ wq,
                                                      const float* __restrict__ bq) {
    __shared__ float2 As[320 * ASP];            // x rows 0..63, h rows 64..319
    __shared__ float2 redA[8 * 8], redC[8 * 8]; // [warp][pair]
    float* Asf = reinterpret_cast<float*>(As);
    const int tid = threadIdx.x;
    const int B0 = blockIdx.x * BM;
    const int wid = tid >> 5, lane = tid & 31;

    for (int i = tid; i < BM * HH; i += 256) {
        int b = i >> 8, k = i & 255;
        Asf[((64 + k) * ASP + (b >> 1)) * 2 + (b & 1)] = h0[(size_t)(B0 + b) * HH + k];
    }
    for (int i = tid; i < BM * FF; i += 256) {
        int b = i >> 6, k = i & 63;
        Asf[(k * ASP + (b >> 1)) * 2 + (b & 1)] = x[((size_t)(B0 + b) * TT + 0) * FF + k];
    }
    const float brz1 = g_brz[tid], brz2 = g_brz[256 + tid];
    const float bi = g_bin[tid], bh = g_bhn[tid];
    const float wqj = wq[tid], bqj = bq[tid];
    const int offx = blockIdx.x & 31;
    const int offh = (blockIdx.x * 37) & 127;
    __syncthreads();

    int q = offx;
    float4 wa = g_W6a[q * 256 + tid];
    float2 wb = g_W6b[q * 256 + tid];

    for (int t = 0; t < TT; t++) {
        // prefetch x_{t+1}
        float xr[4];
#pragma unroll
        for (int r = 0; r < 4; r++) {
            int i = tid + 256 * r;
            int b = i >> 6, k = i & 63;
            xr[r] = (t + 1 < TT) ? x[((size_t)(B0 + b) * TT + (t + 1)) * FF + k] : 0.f;
        }

        u64 aR[8], aZ[8], aI[8], aH[8];
#pragma unroll
        for (int p = 0; p < 8; p++) { aR[p] = 0; aZ[p] = 0; aI[p] = 0; aH[p] = 0; }

        for (int i = 0; i < 32; i++) {               // x-part (k<64): r,z,i_n
            int qn = (i == 31) ? (32 + offh) : ((offx + i + 1) & 31);
            float4 wan = g_W6a[qn * 256 + tid];
            float2 wbn = g_W6b[qn * 256 + tid];
            ENC_STEP6(2 * q, aI);
            wa = wan; wb = wbn; q = qn;
        }
        for (int i = 0; i < 128; i++) {              // h-part (k>=64): r,z,h_n
            int qn = (i == 127) ? offx : (32 + ((offh + i + 1) & 127));
            float4 wan = g_W6a[qn * 256 + tid];
            float2 wbn = g_W6b[qn * 256 + tid];
            ENC_STEP6(2 * q, aH);
            wa = wan; wb = wbn; q = qn;
        }
        __syncthreads();   // all GEMM reads of As done

        // GRU elementwise fully in-register; h update in smem; fp16 hs store;
        // exact attention partials A=wq.h, C=bq.h reduced per warp
        __half* __restrict__ hsh = g_hsh + ((size_t)t * BB + B0) * HH + tid;
#pragma unroll
        for (int p = 0; p < 8; p++) {
            float2 fr = u2f(aR[p]), fz = u2f(aZ[p]), fi = u2f(aI[p]), fh = u2f(aH[p]);
            float2 hp = As[(64 + tid) * ASP + p];
            float r0 = sigf(fr.x + brz1), z0 = sigf(fz.x + brz2);
            float n0 = tanhf(fi.x + bi + r0 * (fh.x + bh));
            float h0n = (1.f - z0) * n0 + z0 * hp.x;
            float r1 = sigf(fr.y + brz1), z1 = sigf(fz.y + brz2);
            float n1 = tanhf(fi.y + bi + r1 * (fh.y + bh));
            float h1n = (1.f - z1) * n1 + z1 * hp.y;
            As[(64 + tid) * ASP + p] = make_float2(h0n, h1n);
            hsh[(size_t)(2 * p) * HH]     = __float2half_rn(h0n);
            hsh[(size_t)(2 * p + 1) * HH] = __float2half_rn(h1n);
            float2 pa = make_float2(wqj * h0n, wqj * h1n);
            float2 pc = make_float2(bqj * h0n, bqj * h1n);
#pragma unroll
            for (int o = 16; o > 0; o >>= 1) {
                pa.x += __shfl_xor_sync(0xffffffffu, pa.x, o);
                pa.y += __shfl_xor_sync(0xffffffffu, pa.y, o);
                pc.x += __shfl_xor_sync(0xffffffffu, pc.x, o);
                pc.y += __shfl_xor_sync(0xffffffffu, pc.y, o);
            }
            if (lane == 0) { redA[wid * 8 + p] = pa; redC[wid * 8 + p] = pc; }
        }
        // store x_{t+1}
#pragma unroll
        for (int r = 0; r < 4; r++) {
            int i = tid + 256 * r;
            int b = i >> 6, k = i & 63;
            Asf[(k * ASP + (b >> 1)) * 2 + (b & 1)] = xr[r];
        }
        __syncthreads();   // As + redA/redC ready

        if (tid < 8) {     // finalize A/C for this block's 16 batches
            float2 A = make_float2(0.f, 0.f), C = make_float2(0.f, 0.f);
#pragma unroll
            for (int w = 0; w < 8; w++) {
                float2 a = redA[w * 8 + tid], c = redC[w * 8 + tid];
                A.x += a.x; A.y += a.y; C.x += c.x; C.y += c.y;
            }
            g_Abt[(size_t)(B0 + 2 * tid) * TT + t]     = A.x * 0.0625f;
            g_Abt[(size_t)(B0 + 2 * tid + 1) * TT + t] = A.y * 0.0625f;
            g_Cbt[(size_t)(B0 + 2 * tid) * TT + t]     = C.x * 0.0625f;
            g_Cbt[(size_t)(B0 + 2 * tid + 1) * TT + t] = C.y * 0.0625f;
        }
    }
}

#define DEC_STEP6(K0) do {                                                                 \
    const double2* _av0 = reinterpret_cast<const double2*>(ctxp + (K0) * 8);               \
    const double2* _av1 = reinterpret_cast<const double2*>(ctxp + ((K0) + 1) * 8);         \
    u64 _p00 = pack2(wa.x), _p01 = pack2(wa.y), _p02 = pack2(wa.z);                        \
    u64 _p10 = pack2(wa.w), _p11 = pack2(wb.x), _p12 = pack2(wb.y);                        \
    _Pragma("unroll")                                                                      \
    for (int _h = 0; _h < 4; _h++) {                                                       \
        double2 _d0 = _av0[_h], _d1 = _av1[_h];                                            \
        u64 _a00 = __double_as_longlong(_d0.x), _a01 = __double_as_longlong(_d0.y);        \
        u64 _a10 = __double_as_longlong(_d1.x), _a11 = __double_as_longlong(_d1.y);        \
        fma2(ar[2*_h],   _p00, _a00); fma2(az[2*_h],   _p01, _a00); fma2(an[2*_h],   _p02, _a00); \
        fma2(ar[2*_h+1], _p00, _a01); fma2(az[2*_h+1], _p01, _a01); fma2(an[2*_h+1], _p02, _a01); \
        fma2(ar[2*_h],   _p10, _a10); fma2(az[2*_h],   _p11, _a10); fma2(an[2*_h],   _p12, _a10); \
        fma2(ar[2*_h+1], _p10, _a11); fma2(az[2*_h+1], _p11, _a11); fma2(an[2*_h+1], _p12, _a11); \
    }                                                                                      \
} while (0)

// ---- persistent decoder: all 32 steps fused ----
__global__ void __launch_bounds__(256) dec_all_kernel(const float* __restrict__ dWih,
                                                      const float* __restrict__ fc1b,
                                                      const float* __restrict__ fc2W,
                                                      const float* __restrict__ fc2b,
                                                      float* __restrict__ out) {
    __shared__ char smraw[8192 + 16384 + 16384 + 64];
    float*  s     = reinterpret_cast<float*>(smraw);                 // [16][128]
    float2* ctxp  = reinterpret_cast<float2*>(smraw + 8192);         // [256][8] pairs
    float*  f1s   = reinterpret_cast<float*>(smraw + 8192);          // overlays ctxp
    float2* hdp   = reinterpret_cast<float2*>(smraw + 8192 + 16384); // [256][8] pairs
    float*  prevs = reinterpret_cast<float*>(smraw + 8192 + 32768);  // [16]
    const int tid = threadIdx.x;
    const int B0 = blockIdx.x * BM;
    const int wid = tid >> 5, lane = tid & 31;
    const int j = tid;
    const int toff = (blockIdx.x * 29) & 127;
    const int qoff = (blockIdx.x * 13) & 127;

    if (tid < BM) prevs[tid] = g_prev[B0 + tid];
    const float dwr = dWih[j], dwz = dWih[256 + j], dwn = dWih[512 + j];
    const float br = g_dbrz[j], bz = g_dbrz[256 + j], bi = g_dbin[j], bh = g_dbhn[j];
    const float b1 = fc1b[tid], fb = fc2b[0];
    float w2r[8];
#pragma unroll
    for (int qq = 0; qq < 8; qq++) w2r[qq] = fc2W[lane + 32 * qq];
    __syncthreads();

    for (int step = 0; step < OL; step++) {
        for (int i = tid; i < BM * TT; i += 256) {
            int b = i >> 7;
            s[i] = prevs[b] * g_Abt[(size_t)B0 * TT + i] + g_Cbt[(size_t)B0 * TT + i];
        }
        __syncthreads();

#pragma unroll
        for (int bb = 0; bb < 2; bb++) {
            int b = wid * 2 + bb;
            float v0 = s[b*TT+lane], v1 = s[b*TT+lane+32], v2 = s[b*TT+lane+64], v3 = s[b*TT+lane+96];
            float m = fmaxf(fmaxf(v0, v1), fmaxf(v2, v3));
#pragma unroll
            for (int o = 16; o > 0; o >>= 1) m = fmaxf(m, __shfl_xor_sync(0xffffffffu, m, o));
            float e0 = __expf(v0-m), e1 = __expf(v1-m), e2 = __expf(v2-m), e3 = __expf(v3-m);
            float sum = e0 + e1 + e2 + e3;
#pragma unroll
            for (int o = 16; o > 0; o >>= 1) sum += __shfl_xor_sync(0xffffffffu, sum, o);
            float inv = 1.f / sum;
            s[b*TT+lane] = e0*inv; s[b*TT+lane+32] = e1*inv; s[b*TT+lane+64] = e2*inv; s[b*TT+lane+96] = e3*inv;
        }
        __syncthreads();

        {   // ctx[b][j] = sum_t w[b,t] * hs_fp16[t][b][j], fp32 packed accumulate
            const int jv = (tid & 63) * 4;
            const int bs = tid >> 6;
            u64 c0[2] = {0,0}, c1[2] = {0,0}, c2[2] = {0,0}, c3[2] = {0,0};
#pragma unroll 4
            for (int i = 0; i < TT; i++) {
                int t = (i + toff) & 127;
                const uint2* hb = reinterpret_cast<const uint2*>(
                    g_hsh + ((size_t)t * BB + B0) * HH) + (jv >> 2);
                float w0 = s[(bs+0)*TT+t], w1 = s[(bs+4)*TT+t], w2 = s[(bs+8)*TT+t], w3 = s[(bs+12)*TT+t];
                uint2 v0 = hb[(bs+0)*64], v1 = hb[(bs+4)*64], v2 = hb[(bs+8)*64], v3 = hb[(bs+12)*64];
                u64 wp0 = pack2(w0), wp1 = pack2(w1), wp2 = pack2(w2), wp3 = pack2(w3);
                fma2(c0[0], wp0, hfp(v0.x)); fma2(c0[1], wp0, hfp(v0.y));
                fma2(c1[0], wp1, hfp(v1.x)); fma2(c1[1], wp1, hfp(v1.y));
                fma2(c2[0], wp2, hfp(v2.x)); fma2(c2[1], wp2, hfp(v2.y));
                fma2(c3[0], wp3, hfp(v3.x)); fma2(c3[1], wp3, hfp(v3.y));
            }
            float* cf = reinterpret_cast<float*>(ctxp);
            u64* cc[4] = {c0, c1, c2, c3};
#pragma unroll
            for (int qq = 0; qq < 4; qq++) {
                int b = bs + 4 * qq, p = b >> 1, par = b & 1;
                float2 lo = u2f(cc[qq][0]), hi = u2f(cc[qq][1]);
                cf[((jv+0)*8+p)*2+par] = lo.x; cf[((jv+1)*8+p)*2+par] = lo.y;
                cf[((jv+2)*8+p)*2+par] = hi.x; cf[((jv+3)*8+p)*2+par] = hi.y;
            }
        }
        __syncthreads();

        u64 ar[8], az[8], an[8];
#pragma unroll
        for (int p = 0; p < 8; p++) { ar[p] = 0; az[p] = 0; an[p] = 0; }
        {   // gh = ctx @ dec_Whh^T (staggered, prefetched)
            int q = qoff;
            float4 wa = g_D6a[q * 256 + tid];
            float2 wb = g_D6b[q * 256 + tid];
            for (int i = 0; i < 128; i++) {
                int qn = (qoff + i + 1) & 127;
                float4 wan = g_D6a[qn * 256 + tid];
                float2 wbn = g_D6b[qn * 256 + tid];
                DEC_STEP6(2 * q);
                wa = wan; wb = wbn; q = qn;
            }
        }
        {   // decoder GRU elementwise (x = prev scalar, h = ctx)
#pragma unroll
            for (int p = 0; p < 8; p++) {
                float2 fr = u2f(ar[p]), fz = u2f(az[p]), fn = u2f(an[p]);
                float2 cx = ctxp[j * 8 + p];
                float2 hd;
                float pv = prevs[2 * p];
                float r = sigf(pv * dwr + fr.x + br);
                float z = sigf(pv * dwz + fz.x + bz);
                float n = tanhf(pv * dwn + bi + r * (fn.x + bh));
                hd.x = (1.f - z) * n + z * cx.x;
                pv = prevs[2 * p + 1];
                r = sigf(pv * dwr + fr.y + br);
                z = sigf(pv * dwz + fz.y + bz);
                n = tanhf(pv * dwn + bi + r * (fn.y + bh));
                hd.y = (1.f - z) * n + z * cx.y;
                hdp[j * 8 + p] = hd;
            }
        }
        __syncthreads();   // hdp ready; ctxp reusable as f1s

        {   // fc1 + relu (staggered, prefetched)
            u64 f[8];
#pragma unroll
            for (int p = 0; p < 8; p++) f[p] = 0;
            int q = qoff;
            float2 wf = g_F2[q * 256 + tid];
            for (int i = 0; i < 128; i++) {
                int qn = (qoff + i + 1) & 127;
                float2 wfn = g_F2[qn * 256 + tid];
                const double2* hv0 = reinterpret_cast<const double2*>(hdp + (2 * q) * 8);
                const double2* hv1 = reinterpret_cast<const double2*>(hdp + (2 * q + 1) * 8);
                u64 w0 = pack2(wf.x), w1 = pack2(wf.y);
#pragma unroll
                for (int h = 0; h < 4; h++) {
                    double2 d0 = hv0[h], d1 = hv1[h];
                    fma2(f[2*h],   w0, __double_as_longlong(d0.x));
                    fma2(f[2*h+1], w0, __double_as_longlong(d0.y));
                    fma2(f[2*h],   w1, __double_as_longlong(d1.x));
                    fma2(f[2*h+1], w1, __double_as_longlong(d1.y));
                }
                wf = wfn; q = qn;
            }
#pragma unroll
            for (int p = 0; p < 8; p++) {
                float2 v = u2f(f[p]);
                f1s[(2*p)*FCH + tid]   = fmaxf(v.x + b1, 0.f);
                f1s[(2*p+1)*FCH + tid] = fmaxf(v.y + b1, 0.f);
            }
        }
        __syncthreads();

        {   // fc2: warp reduces 2 batches; carry prev in smem
#pragma unroll
            for (int bb = 0; bb < 2; bb++) {
                int b = wid * 2 + bb;
                float a = 0.f;
#pragma unroll
                for (int qq = 0; qq < 8; qq++)
                    a += f1s[b * FCH + lane + 32 * qq] * w2r[qq];
#pragma unroll
                for (int o = 16; o > 0; o >>= 1) a += __shfl_xor_sync(0xffffffffu, a, o);
                if (lane == 0) {
                    float v = a + fb;
                    out[(size_t)(B0 + b) * OL + step] = v;
                    prevs[b] = v;
                }
            }
        }
        __syncthreads();
    }
}

extern "C" void kernel_launch(void* const* d_in, const int* in_sizes, int n_in,
                              void* d_out, int out_size) {
    const float* x      = (const float*)d_in[0];
    const float* h      = (const float*)d_in[1];
    const float* eWih   = (const float*)d_in[2];
    const float* eWhh   = (const float*)d_in[3];
    const float* ebih   = (const float*)d_in[4];
    const float* ebhh   = (const float*)d_in[5];
    const float* dWih   = (const float*)d_in[6];
    const float* dWhh   = (const float*)d_in[7];
    const float* dbih   = (const float*)d_in[8];
    const float* dbhh   = (const float*)d_in[9];
    const float* wq     = (const float*)d_in[10];
    const float* bq     = (const float*)d_in[11];
    const float* fc1W   = (const float*)d_in[12];
    const float* fc1b   = (const float*)d_in[13];
    const float* fc2W   = (const float*)d_in[14];
    const float* fc2b   = (const float*)d_in[15];
    float* out = (float*)d_out;

    prep_kernel<<<256, 256>>>(x, eWih, eWhh, ebih, ebhh, dWhh, dbih, dbhh, fc1W);
    enc_all_kernel<<<BB / BM, 256>>>(x, h, wq, bq);
    dec_all_kernel<<<BB / BM, 256>>>(dWih, fc1b, fc2W, fc2b, out);
}